// round 2
// baseline (speedup 1.0000x reference)
#include <cuda_runtime.h>

#define BB 4
#define NN 2048
#define FIN 128
#define HH 4
#define DKK 32
#define TI 64
#define TJ 64
#define NW (NN/32)          // 64 bit-words per adj row

// Scratch (no cudaMalloc allowed)
__device__ float g_h[BB*HH*NN*DKK];        // [B][H][N][DK]  4 MB
__device__ float g_el[BB*HH*NN];
__device__ float g_er[BB*HH*NN];
__device__ unsigned int g_bits[BB*NN*NW];  // 2 MB bitmask

// ---------------------------------------------------------------------------
// Kernel A: pack adj (int32 0/1, 67 MB) -> bitmask (2 MB). Read adj exactly once.
// ---------------------------------------------------------------------------
__global__ void pack_adj_k(const int* __restrict__ adj) {
    int gw    = (blockIdx.x * blockDim.x + threadIdx.x) >> 5;
    int lane  = threadIdx.x & 31;
    int nwrps = (gridDim.x * blockDim.x) >> 5;
    const int total = BB * NN * NW;
    for (int w = gw; w < total; w += nwrps) {
        int v = adj[(long long)w * 32 + lane];
        unsigned int m = __ballot_sync(0xffffffffu, v != 0);
        if (lane == 0) g_bits[w] = m;
    }
}

// ---------------------------------------------------------------------------
// Kernel B: h[b,h,n,d] = sum_i x[b,n,i] * W[h,i,d]
// Block = 32 rows (n) x 256 threads; thread owns column c=(h,d) and 16 rows.
// ---------------------------------------------------------------------------
__global__ __launch_bounds__(256) void compute_h_k(const float* __restrict__ x,
                                                   const float* __restrict__ W) {
    __shared__ float xs[32][FIN];
    int t = threadIdx.x;
    int row0 = blockIdx.x * 32;          // global row over B*N
    for (int idx = t; idx < 32 * FIN; idx += 256)
        xs[idx >> 7][idx & 127] = x[(long long)row0 * FIN + idx];
    __syncthreads();

    int c  = t & 127;
    int hh = c >> 5;
    int d  = c & 31;
    int rb = (t >> 7) * 16;

    float acc[16];
#pragma unroll
    for (int r = 0; r < 16; r++) acc[r] = 0.f;

    const float* Wc = W + hh * FIN * DKK + d;
#pragma unroll 8
    for (int i = 0; i < FIN; i++) {
        float wv = __ldg(Wc + i * DKK);
#pragma unroll
        for (int r = 0; r < 16; r++) acc[r] += xs[rb + r][i] * wv;
    }

    int b  = row0 / NN;
    int n0 = row0 % NN;
#pragma unroll
    for (int r = 0; r < 16; r++) {
        int n = n0 + rb + r;
        g_h[(((b * HH + hh) * NN) + n) * DKK + d] = acc[r];
    }
}

// ---------------------------------------------------------------------------
// Kernel C: el/er per (b,h,n): 32-wide dot with a_l / a_r, shfl reduce.
// ---------------------------------------------------------------------------
__global__ void compute_lr_k(const float* __restrict__ a) {
    int warp = (blockIdx.x * blockDim.x + threadIdx.x) >> 5;
    int lane = threadIdx.x & 31;
    if (warp >= BB * HH * NN) return;
    int hh = (warp / NN) % HH;
    float v  = g_h[warp * DKK + lane];
    float al = a[hh * 2 * DKK + lane];
    float ar = a[hh * 2 * DKK + DKK + lane];
    float el = v * al, er = v * ar;
#pragma unroll
    for (int o = 16; o > 0; o >>= 1) {
        el += __shfl_xor_sync(0xffffffffu, el, o);
        er += __shfl_xor_sync(0xffffffffu, er, o);
    }
    if (lane == 0) { g_el[warp] = el; g_er[warp] = er; }
}

// ---------------------------------------------------------------------------
// Kernel D: fused masked-softmax + aggregate (flash-GAT).
// Block = (b, h, 64-row i-tile). leaky_relu monotonic + bounded logits
// => no max subtraction needed. Phase A: P[j][i]=masked exp (each exp once).
// Phase B: acc += P * H via packed fma.rn.f32x2 (2x fp32 FMA throughput).
// Output layout: reference reshapes contiguous (B,H,N,DK) -> (B,N,H*DK)
// WITHOUT transposing, so we write flat (b,h,n,d) order.
// ---------------------------------------------------------------------------
__global__ __launch_bounds__(256) void gat_attn_k(float* __restrict__ out) {
    __shared__ float Ps[TJ * TI];            // [j][i] 16 KB
    __shared__ float Hs[TJ * DKK];           // 8 KB
    __shared__ float er_s[NN];               // 8 KB
    __shared__ unsigned int bitw_s[TI * 2];  // current tile's bit words
    __shared__ float el_s[TI];
    __shared__ float ssum_s[4 * TI];
    __shared__ float inv_s[TI];

    int t   = threadIdx.x;
    int bid = blockIdx.x;
    const int nIT = NN / TI;                 // 32
    int it = bid % nIT;
    int hh = (bid / nIT) % HH;
    int b  = bid / (nIT * HH);
    int ibase = it * TI;

    const float* hrow = g_h + (long long)((b * HH + hh) * NN) * DKK;
    const float* erow = g_er + (b * HH + hh) * NN;
    const float* elow = g_el + (b * HH + hh) * NN + ibase;
    const unsigned int* brow = g_bits + (long long)(b * NN + ibase) * NW;

    for (int idx = t; idx < NN; idx += 256) er_s[idx] = erow[idx];
    if (t < TI) el_s[t] = elow[t];

    int w = t >> 5, lane = t & 31;
    int ia = t & 63;                         // phase-A fixed row
    int jb = t >> 6;                         // phase-A j sub-offset 0..3

    unsigned long long acc0 = 0, acc1 = 0, acc2 = 0, acc3 = 0;
    float psum = 0.f;

    __syncthreads();
    float el_i = el_s[ia];

    for (int jt = 0; jt < NN / TJ; jt++) {
        // ---- stage H tile + bit words ----
        {
            const float4* src = (const float4*)(hrow + (long long)(jt * TJ) * DKK);
            float4* dst = (float4*)Hs;
            dst[t]       = src[t];
            dst[t + 256] = src[t + 256];
            if (t < TI * 2)
                bitw_s[t] = brow[(t >> 1) * NW + jt * 2 + (t & 1)];
        }
        __syncthreads();

        // ---- Phase A: P[j][i] = adj ? exp(lrelu(el_i + er_j)) : 0 ----
#pragma unroll
        for (int k = 0; k < 16; k++) {
            int j = k * 4 + jb;
            unsigned int wrd = bitw_s[ia * 2 + (j >> 5)];
            float e = el_i + er_s[jt * TJ + j];
            float l = fmaxf(e, 0.2f * e);
            float p = ((wrd >> (j & 31)) & 1u) ? __expf(l) : 0.f;
            Ps[j * TI + ia] = p;
            psum += p;
        }
        __syncthreads();

        // ---- Phase B: acc[i][d] += P[j][i] * Hs[j][d]  (FFMA2) ----
        {
            const float* hp = Hs + lane;
            const float* pp = Ps + 8 * w;
#pragma unroll 4
            for (int j = 0; j < TJ; j++) {
                float hv = hp[j * DKK];
                unsigned int hu = __float_as_uint(hv);
                unsigned long long h2;
                asm("mov.b64 %0, {%1, %1};" : "=l"(h2) : "r"(hu));
                const ulonglong2* pv = (const ulonglong2*)(pp + j * TI);
                ulonglong2 pA = pv[0];
                ulonglong2 pB = pv[1];
                asm("fma.rn.f32x2 %0, %1, %2, %0;" : "+l"(acc0) : "l"(pA.x), "l"(h2));
                asm("fma.rn.f32x2 %0, %1, %2, %0;" : "+l"(acc1) : "l"(pA.y), "l"(h2));
                asm("fma.rn.f32x2 %0, %1, %2, %0;" : "+l"(acc2) : "l"(pB.x), "l"(h2));
                asm("fma.rn.f32x2 %0, %1, %2, %0;" : "+l"(acc3) : "l"(pB.y), "l"(h2));
            }
        }
        __syncthreads();
    }

    // ---- row-sum reduce (4 partials per i) ----
    ssum_s[jb * TI + ia] = psum;
    __syncthreads();
    if (t < TI) {
        float s = ssum_s[t] + ssum_s[TI + t] + ssum_s[2 * TI + t] + ssum_s[3 * TI + t];
        inv_s[t] = 1.f / s;
    }
    __syncthreads();

    // ---- write normalized output: flat (b, h, n, d) order ----
    float* obase = out + (long long)(((b * HH + hh) * NN) + ibase) * DKK + lane;
    unsigned long long accs[4] = {acc0, acc1, acc2, acc3};
#pragma unroll
    for (int k = 0; k < 4; k++) {
        int r0 = 8 * w + 2 * k;
        float lo = __uint_as_float((unsigned int)accs[k]);
        float hi = __uint_as_float((unsigned int)(accs[k] >> 32));
        obase[(long long)r0 * DKK]       = lo * inv_s[r0];
        obase[(long long)(r0 + 1) * DKK] = hi * inv_s[r0 + 1];
    }
}

// ---------------------------------------------------------------------------
extern "C" void kernel_launch(void* const* d_in, const int* in_sizes, int n_in,
                              void* d_out, int out_size) {
    const float* x   = (const float*)d_in[0];
    const int*   adj = (const int*)d_in[1];
    const float* W   = (const float*)d_in[2];
    const float* a   = (const float*)d_in[3];
    float* out = (float*)d_out;

    pack_adj_k<<<2048, 256>>>(adj);
    compute_h_k<<<(BB * NN) / 32, 256>>>(x, W);
    compute_lr_k<<<(BB * HH * NN) / 8, 256>>>(a);
    gat_attn_k<<<BB * HH * (NN / TI), 256>>>(out);
}

// round 3
// speedup vs baseline: 1.1829x; 1.1829x over previous
#include <cuda_runtime.h>

#define BB 4
#define NN 2048
#define FIN 128
#define HH 4
#define DKK 32
#define NW (NN/32)           // 64 bit-words per adj row
#define TJ 256               // j-tile staged to smem
#define LOG2E 1.4426950408889634f

// Scratch (no cudaMalloc allowed)
__device__ float g_h[BB*HH*NN*DKK];        // [B][H][N][DK]  4 MB
__device__ float g_el[BB*HH*NN];           // pre-scaled by LOG2E
__device__ float g_er[BB*HH*NN];           // pre-scaled by LOG2E
__device__ unsigned int g_bits[BB*NW*NN];  // TRANSPOSED: [b][word_j][i]  2 MB

// ---------------------------------------------------------------------------
// Kernel A: pack adj (67 MB, read once) -> transposed bitmask [b][wj][i].
// Transposed so the attention kernel's per-warp word load is coalesced.
// ---------------------------------------------------------------------------
__global__ void pack_adj_k(const int* __restrict__ adj) {
    int gw    = (blockIdx.x * blockDim.x + threadIdx.x) >> 5;
    int lane  = threadIdx.x & 31;
    int nwrps = (gridDim.x * blockDim.x) >> 5;
    const int total = BB * NW * NN;
    for (int w = gw; w < total; w += nwrps) {
        int i  = w % NN;
        int wj = (w / NN) % NW;
        int b  = w / (NN * NW);
        int v = adj[((long long)(b * NN + i)) * NN + wj * 32 + lane];
        unsigned int m = __ballot_sync(0xffffffffu, v != 0);
        if (lane == 0) g_bits[w] = m;
    }
}

// ---------------------------------------------------------------------------
// Kernel B: h[b,h,n,d] = sum_i x[b,n,i] * W[h,i,d]
// ---------------------------------------------------------------------------
__global__ __launch_bounds__(256) void compute_h_k(const float* __restrict__ x,
                                                   const float* __restrict__ W) {
    __shared__ float xs[32][FIN];
    int t = threadIdx.x;
    int row0 = blockIdx.x * 32;
    for (int idx = t; idx < 32 * FIN; idx += 256)
        xs[idx >> 7][idx & 127] = x[(long long)row0 * FIN + idx];
    __syncthreads();

    int c  = t & 127;
    int hh = c >> 5;
    int d  = c & 31;
    int rb = (t >> 7) * 16;

    float acc[16];
#pragma unroll
    for (int r = 0; r < 16; r++) acc[r] = 0.f;

    const float* Wc = W + hh * FIN * DKK + d;
#pragma unroll 8
    for (int i = 0; i < FIN; i++) {
        float wv = __ldg(Wc + i * DKK);
#pragma unroll
        for (int r = 0; r < 16; r++) acc[r] += xs[rb + r][i] * wv;
    }

    int b  = row0 / NN;
    int n0 = row0 % NN;
#pragma unroll
    for (int r = 0; r < 16; r++) {
        int n = n0 + rb + r;
        g_h[(((b * HH + hh) * NN) + n) * DKK + d] = acc[r];
    }
}

// ---------------------------------------------------------------------------
// Kernel C: el/er per (b,h,n), pre-scaled by LOG2E so attn uses ex2 directly.
// ---------------------------------------------------------------------------
__global__ void compute_lr_k(const float* __restrict__ a) {
    int warp = (blockIdx.x * blockDim.x + threadIdx.x) >> 5;
    int lane = threadIdx.x & 31;
    if (warp >= BB * HH * NN) return;
    int hh = (warp / NN) % HH;
    float v  = g_h[warp * DKK + lane];
    float al = a[hh * 2 * DKK + lane];
    float ar = a[hh * 2 * DKK + DKK + lane];
    float el = v * al, er = v * ar;
#pragma unroll
    for (int o = 16; o > 0; o >>= 1) {
        el += __shfl_xor_sync(0xffffffffu, el, o);
        er += __shfl_xor_sync(0xffffffffu, er, o);
    }
    if (lane == 0) { g_el[warp] = el * LOG2E; g_er[warp] = er * LOG2E; }
}

// ---------------------------------------------------------------------------
// Kernel D: fused masked-softmax + aggregate, register-resident P.
// Block = (b, h, 32-row i-tile); 8 warps. lane = i, regs = d-pairs (f32x2).
// Warp w covers j in {jt*256 + w*32 + [0,32)} across 8 tiles -> disjoint j,
// partial accs reduced across warps at the end.
// Per (warp,j): inline masked exp (regs only) + 8 broadcast LDS.128 of h[j]
// + 16 fma.rn.f32x2. No smem P, no inner barriers.
// ---------------------------------------------------------------------------
__global__ __launch_bounds__(256) void gat_attn_k(float* __restrict__ out) {
    __shared__ float Hs[TJ * DKK];     // 32 KB: staged h tile, reused as red buf
    __shared__ float er_s[NN];         // 8 KB: er' for (b,h); reused for transpose
    __shared__ float psum_s[256];
    __shared__ float inv_s[32];

    int t    = threadIdx.x;
    int w    = t >> 5;
    int lane = t & 31;
    int bid  = blockIdx.x;
    int it = bid & 63;                 // NN/32 = 64 i-tiles
    int hh = (bid >> 6) & 3;
    int b  = bid >> 8;
    int ibase = it * 32;
    int bh = b * HH + hh;

    const float* hrow = g_h + (long long)bh * NN * DKK;

    // stage er' (full row for this (b,h))
    {
        const float4* esrc = (const float4*)(g_er + bh * NN);
        float4* edst = (float4*)er_s;
        edst[t] = esrc[t];
        edst[t + 256] = esrc[t + 256];
    }
    float el = g_el[bh * NN + ibase + lane];   // per-lane i, via L2 broadcast

    unsigned long long acc[16];
#pragma unroll
    for (int r = 0; r < 16; r++) acc[r] = 0ull;
    float psum = 0.f;

    for (int jt = 0; jt < NN / TJ; jt++) {
        // stage H tile (256 j-rows x 32 d = 32 KB), coalesced
        {
            const float4* src = (const float4*)(hrow + (long long)jt * TJ * DKK);
            float4* dst = (float4*)Hs;
#pragma unroll
            for (int k = 0; k < 8; k++) dst[t + k * 256] = src[t + k * 256];
        }
        // bit word for (i=lane, j in warp's 32-j slice): coalesced LDG
        unsigned int wrd = g_bits[((long long)b * NW + jt * 8 + w) * NN + ibase + lane];
        __syncthreads();

        const float* hbase = Hs + (w * 32) * DKK;
        const float4* erp = (const float4*)(er_s + jt * TJ + w * 32);

#pragma unroll
        for (int jq = 0; jq < 8; jq++) {
            float4 er4 = erp[jq];
            float ev[4] = {er4.x, er4.y, er4.z, er4.w};
#pragma unroll
            for (int s = 0; s < 4; s++) {
                int jj = jq * 4 + s;
                float e  = el + ev[s];
                float lr = fmaxf(e, 0.2f * e);
                float pe;
                asm("ex2.approx.f32 %0, %1;" : "=f"(pe) : "f"(lr));
                float p = (wrd & (1u << jj)) ? pe : 0.0f;
                psum += p;
                unsigned long long p2;
                asm("mov.b64 %0, {%1, %1};" : "=l"(p2) : "r"(__float_as_uint(p)));
                const ulonglong2* hp = (const ulonglong2*)(hbase + jj * DKK);
#pragma unroll
                for (int r = 0; r < 4; r++) {
                    ulonglong2 hv = hp[r];
                    asm("fma.rn.f32x2 %0, %1, %2, %0;" : "+l"(acc[2*r])   : "l"(hv.x), "l"(p2));
                    asm("fma.rn.f32x2 %0, %1, %2, %0;" : "+l"(acc[2*r+1]) : "l"(hv.y), "l"(p2));
                }
                const ulonglong2* hp2 = hp + 4;
#pragma unroll
                for (int r = 4; r < 8; r++) {
                    ulonglong2 hv = hp2[r - 4];
                    asm("fma.rn.f32x2 %0, %1, %2, %0;" : "+l"(acc[2*r])   : "l"(hv.x), "l"(p2));
                    asm("fma.rn.f32x2 %0, %1, %2, %0;" : "+l"(acc[2*r+1]) : "l"(hv.y), "l"(p2));
                }
            }
        }
        __syncthreads();
    }

    // ---- cross-warp reduction: red[w][d][i] (conflict-free stores) ----
    float* red = Hs;
#pragma unroll
    for (int r = 0; r < 16; r++) {
        float lo = __uint_as_float((unsigned int)acc[r]);
        float hi = __uint_as_float((unsigned int)(acc[r] >> 32));
        red[w * 1024 + (2 * r) * 32 + lane]     = lo;
        red[w * 1024 + (2 * r + 1) * 32 + lane] = hi;
    }
    psum_s[w * 32 + lane] = psum;
    __syncthreads();

    if (t < 32) {
        float s = 0.f;
#pragma unroll
        for (int ww = 0; ww < 8; ww++) s += psum_s[ww * 32 + t];
        inv_s[t] = 1.f / s;
    }

    // raw 8-way sums (independent of inv_s)
    float vals[4];
#pragma unroll
    for (int k = 0; k < 4; k++) {
        int o = t + k * 256;               // o = d*32 + i
        float s = 0.f;
#pragma unroll
        for (int ww = 0; ww < 8; ww++) s += red[ww * 1024 + o];
        vals[k] = s;
    }
    __syncthreads();                       // inv_s visible

    // transpose via padded buffer (reuse er_s) for coalesced output
    float* fin = er_s;                     // needs 32*33 = 1056 floats
#pragma unroll
    for (int k = 0; k < 4; k++) {
        int o = t + k * 256;
        int d = o >> 5, i = o & 31;
        fin[i * 33 + d] = vals[k] * inv_s[i];
    }
    __syncthreads();

    float* obase = out + (long long)(bh * NN + ibase) * DKK;
#pragma unroll
    for (int k = 0; k < 4; k++) {
        int q = t + k * 256;               // q = i*32 + d
        obase[q] = fin[(q >> 5) * 33 + (q & 31)];
    }
}

// ---------------------------------------------------------------------------
extern "C" void kernel_launch(void* const* d_in, const int* in_sizes, int n_in,
                              void* d_out, int out_size) {
    const float* x   = (const float*)d_in[0];
    const int*   adj = (const int*)d_in[1];
    const float* W   = (const float*)d_in[2];
    const float* a   = (const float*)d_in[3];
    float* out = (float*)d_out;

    pack_adj_k<<<2048, 256>>>(adj);
    compute_h_k<<<(BB * NN) / 32, 256>>>(x, W);
    compute_lr_k<<<(BB * HH * NN) / 8, 256>>>(a);
    gat_attn_k<<<BB * HH * (NN / 32), 256>>>(out);
}

// round 5
// speedup vs baseline: 2.0745x; 1.7538x over previous
#include <cuda_runtime.h>
#include <cstdint>

#define BB 4
#define NN 2048
#define FIN 128
#define HH 4
#define DKK 32
#define NW (NN/32)
#define LOG2E 1.4426950408889634f

// Scratch (no cudaMalloc allowed)
__device__ float g_h[BB*HH*NN*DKK];        // [bh][n][d] fp32 (for el/er)
__device__ float g_hT[BB*HH*DKK*NN];       // [bh][d][n] tf32-rounded (MMA B)
__device__ float g_el[BB*HH*NN];           // pre-scaled by LOG2E
__device__ float g_er[BB*HH*NN];           // pre-scaled by LOG2E
__device__ unsigned int g_bits[BB*NW*NN];  // transposed bitmask [b][wj][i]

// ---------------------------------------------------------------------------
// Kernel A: pack adj (67 MB, read once) -> transposed bitmask [b][wj][i].
// ---------------------------------------------------------------------------
__global__ void pack_adj_k(const int* __restrict__ adj) {
    int gw    = (blockIdx.x * blockDim.x + threadIdx.x) >> 5;
    int lane  = threadIdx.x & 31;
    int nwrps = (gridDim.x * blockDim.x) >> 5;
    const int total = BB * NW * NN;
    for (int w = gw; w < total; w += nwrps) {
        int i  = w % NN;
        int wj = (w / NN) % NW;
        int b  = w / (NN * NW);
        int v = adj[((long long)(b * NN + i)) * NN + wj * 32 + lane];
        unsigned int m = __ballot_sync(0xffffffffu, v != 0);
        if (lane == 0) g_bits[w] = m;
    }
}

// ---------------------------------------------------------------------------
// Kernel B: h = x @ W; writes g_h (fp32, [n][d]) and g_hT (tf32, [d][n]
// via smem transpose for coalesced stores).
// ---------------------------------------------------------------------------
__global__ __launch_bounds__(256) void compute_h_k(const float* __restrict__ x,
                                                   const float* __restrict__ W) {
    __shared__ float xs[32][FIN];
    __shared__ float sT[128][33];       // [c=(hh,d)][n-within-block]
    int t = threadIdx.x;
    int row0 = blockIdx.x * 32;
    for (int idx = t; idx < 32 * FIN; idx += 256)
        xs[idx >> 7][idx & 127] = x[(long long)row0 * FIN + idx];
    __syncthreads();

    int c  = t & 127;
    int hh = c >> 5;
    int d  = c & 31;
    int rb = (t >> 7) * 16;

    float acc[16];
#pragma unroll
    for (int r = 0; r < 16; r++) acc[r] = 0.f;

    const float* Wc = W + hh * FIN * DKK + d;
#pragma unroll 8
    for (int i = 0; i < FIN; i++) {
        float wv = __ldg(Wc + i * DKK);
#pragma unroll
        for (int r = 0; r < 16; r++) acc[r] += xs[rb + r][i] * wv;
    }

    int b  = row0 / NN;
    int n0 = row0 % NN;
    int bh = b * HH + hh;
#pragma unroll
    for (int r = 0; r < 16; r++)
        g_h[((long long)bh * NN + n0 + rb + r) * DKK + d] = acc[r];

#pragma unroll
    for (int r = 0; r < 16; r++) {
        unsigned tv;
        asm("cvt.rna.tf32.f32 %0, %1;" : "=r"(tv) : "f"(acc[r]));
        sT[c][rb + r] = __uint_as_float(tv);
    }
    __syncthreads();

    // coalesced write of hT: each float4 = 4 consecutive n for a (hh,d) row
#pragma unroll
    for (int k = 0; k < 4; k++) {
        int q = t + k * 256;            // 0..1023: row = q>>3, seg = q&7
        int row = q >> 3, seg = q & 7;
        int hh2 = row >> 5, d2 = row & 31;
        float4 v = make_float4(sT[row][seg * 4], sT[row][seg * 4 + 1],
                               sT[row][seg * 4 + 2], sT[row][seg * 4 + 3]);
        *(float4*)(g_hT + ((long long)(b * HH + hh2) * DKK + d2) * NN + n0 + seg * 4) = v;
    }
}

// ---------------------------------------------------------------------------
// Kernel C: el/er per (b,h,n), pre-scaled by LOG2E.
// ---------------------------------------------------------------------------
__global__ void compute_lr_k(const float* __restrict__ a) {
    int warp = (blockIdx.x * blockDim.x + threadIdx.x) >> 5;
    int lane = threadIdx.x & 31;
    if (warp >= BB * HH * NN) return;
    int hh = (warp / NN) % HH;
    float v  = g_h[(long long)warp * DKK + lane];
    float al = a[hh * 2 * DKK + lane];
    float ar = a[hh * 2 * DKK + DKK + lane];
    float el = v * al, er = v * ar;
#pragma unroll
    for (int o = 16; o > 0; o >>= 1) {
        el += __shfl_xor_sync(0xffffffffu, el, o);
        er += __shfl_xor_sync(0xffffffffu, er, o);
    }
    if (lane == 0) { g_el[warp] = el * LOG2E; g_er[warp] = er * LOG2E; }
}

// ---------------------------------------------------------------------------
// Kernel D: fused masked-softmax + aggregate via mma.sync tf32 m16n8k8.
// Block = (b, h, 64-i tile), 8 warps. Warp w: rows (w&3)*16, j-half w>>2.
// P generated straight into A fragments (never touches smem). H^T staged
// fragment-ordered in smem (conflict-free LDS.64). psum reduced by 2 shfls.
// ---------------------------------------------------------------------------
__device__ __forceinline__ unsigned p_gen(float el, float er, unsigned m, float& ps) {
    float e = el + er;
    float l = fmaxf(e, 0.2f * e);
    float pe;
    asm("ex2.approx.f32 %0, %1;" : "=f"(pe) : "f"(l));
    float p = m ? pe : 0.f;
    unsigned u;
    asm("cvt.rna.tf32.f32 %0, %1;" : "=r"(u) : "f"(p));
    ps += __uint_as_float(u);
    return u;
}

__global__ __launch_bounds__(256) void gat_attn_mma_k(float* __restrict__ out) {
    __shared__ float er_s[NN];              // 8 KB
    __shared__ float Bf[2 * 16 * 264];      // 33 KB fragment-ordered H^T (2 halves)

    int t = threadIdx.x, w = t >> 5, lane = t & 31;
    int bid = blockIdx.x;
    int it = bid & 31;                       // 32 i-tiles of 64
    int hh = (bid >> 5) & 3;
    int b  = bid >> 7;
    int bh = b * HH + hh;
    int ibase = it * 64;

    int half = w >> 2;                       // j-half this warp covers
    int iw   = ibase + (w & 3) * 16;         // warp's first i-row
    int r    = lane >> 2;                    // row-in-group 0..7
    int c0   = lane & 3;

    // stage er row
    {
        float4* edst = (float4*)er_s;
        const float4* esrc = (const float4*)(g_er + (long long)bh * NN);
        edst[t] = esrc[t];
        edst[t + 256] = esrc[t + 256];
    }
    float el_lo = g_el[(long long)bh * NN + iw + r];
    float el_hi = g_el[(long long)bh * NN + iw + r + 8];

    float acc[4][4];
#pragma unroll
    for (int nt = 0; nt < 4; nt++)
#pragma unroll
        for (int q = 0; q < 4; q++) acc[nt][q] = 0.f;
    float psl = 0.f, psh = 0.f;

    const float* hTb = g_hT + (long long)bh * DKK * NN;
    int sh   = t >> 7;                       // staging half (0/1)
    int tt   = t & 127;
    int skc  = tt >> 3;
    int sjj  = tt & 7;
    int sb01 = sjj >> 2;

    const unsigned* bitb = g_bits + (long long)b * NW * NN;

    for (int mt = 0; mt < 8; mt++) {
        __syncthreads();                     // previous consumption done
        // ---- stage Bf: fragment-ordered H^T for both halves ----
        {
            int jsrc = sh * 1024 + mt * 128 + tt;
#pragma unroll 8
            for (int k = 0; k < 32; k++) {
                float v = hTb[(long long)k * NN + jsrc];
                int lane_d = ((k & 7) << 2) + (tt & 3);
                Bf[sh * 4224 + skc * 264 + (k >> 3) * 64 + lane_d * 2 + sb01] = v;
            }
        }
        __syncthreads();

        int joff = half * 1024 + mt * 128;
        const float* bfh = Bf + half * 4224 + lane * 2;
        unsigned wrd_lo = 0, wrd_hi = 0;

#pragma unroll 4
        for (int kc = 0; kc < 16; kc++) {
            if ((kc & 3) == 0) {
                int jw = half * 32 + mt * 4 + (kc >> 2);
                wrd_lo = bitb[(long long)jw * NN + iw + r];
                wrd_hi = bitb[(long long)jw * NN + iw + r + 8];
            }
            float e0 = er_s[joff + kc * 8 + c0];
            float e4 = er_s[joff + kc * 8 + c0 + 4];
            int j0 = (kc & 3) * 8 + c0;

            unsigned a0 = p_gen(el_lo, e0, (wrd_lo >> j0) & 1u, psl);
            unsigned a1 = p_gen(el_hi, e0, (wrd_hi >> j0) & 1u, psh);
            unsigned a2 = p_gen(el_lo, e4, (wrd_lo >> (j0 + 4)) & 1u, psl);
            unsigned a3 = p_gen(el_hi, e4, (wrd_hi >> (j0 + 4)) & 1u, psh);

            const float2* bp = (const float2*)(bfh + kc * 264);
#pragma unroll
            for (int nt = 0; nt < 4; nt++) {
                float2 bv = bp[nt * 32];
                unsigned b0 = __float_as_uint(bv.x);
                unsigned b1 = __float_as_uint(bv.y);
                asm("mma.sync.aligned.m16n8k8.row.col.f32.tf32.tf32.f32 "
                    "{%0,%1,%2,%3}, {%4,%5,%6,%7}, {%8,%9}, {%0,%1,%2,%3};"
                    : "+f"(acc[nt][0]), "+f"(acc[nt][1]),
                      "+f"(acc[nt][2]), "+f"(acc[nt][3])
                    : "r"(a0), "r"(a1), "r"(a2), "r"(a3), "r"(b0), "r"(b1));
            }
        }
    }

    // ---- combine the two j-halves (warps w and w+4) ----
    __syncthreads();
    float* red = Bf;
    if (w >= 4) {
        int base = ((w - 4) * 32 + lane) * 19;
#pragma unroll
        for (int nt = 0; nt < 4; nt++)
#pragma unroll
            for (int q = 0; q < 4; q++) red[base + nt * 4 + q] = acc[nt][q];
        red[base + 16] = psl;
        red[base + 17] = psh;
    }
    __syncthreads();
    if (w < 4) {
        int base = (w * 32 + lane) * 19;
#pragma unroll
        for (int nt = 0; nt < 4; nt++)
#pragma unroll
            for (int q = 0; q < 4; q++) acc[nt][q] += red[base + nt * 4 + q];
        psl += red[base + 16];
        psh += red[base + 17];

        // quad reduce psums (lanes of a quad hold disjoint col-partials)
        psl += __shfl_xor_sync(0xffffffffu, psl, 1);
        psl += __shfl_xor_sync(0xffffffffu, psl, 2);
        psh += __shfl_xor_sync(0xffffffffu, psh, 1);
        psh += __shfl_xor_sync(0xffffffffu, psh, 2);
        float invl = 1.f / psl;
        float invh = 1.f / psh;

        float* ob = out + ((long long)bh * NN + iw + r) * DKK;
#pragma unroll
        for (int nt = 0; nt < 4; nt++) {
            int col = nt * 8 + 2 * c0;
            float2 v0 = make_float2(acc[nt][0] * invl, acc[nt][1] * invl);
            float2 v1 = make_float2(acc[nt][2] * invh, acc[nt][3] * invh);
            *(float2*)(ob + col) = v0;
            *(float2*)(ob + 8 * DKK + col) = v1;
        }
    }
}

// ---------------------------------------------------------------------------
extern "C" void kernel_launch(void* const* d_in, const int* in_sizes, int n_in,
                              void* d_out, int out_size) {
    const float* x   = (const float*)d_in[0];
    const int*   adj = (const int*)d_in[1];
    const float* W   = (const float*)d_in[2];
    const float* a   = (const float*)d_in[3];
    float* out = (float*)d_out;

    pack_adj_k<<<2048, 256>>>(adj);
    compute_h_k<<<(BB * NN) / 32, 256>>>(x, W);
    compute_lr_k<<<(BB * HH * NN) / 8, 256>>>(a);
    gat_attn_mma_k<<<BB * HH * 32, 256>>>(out);
}

// round 9
// speedup vs baseline: 2.2792x; 1.0987x over previous
#include <cuda_runtime.h>
#include <cstdint>

#define BB 4
#define NN 2048
#define FIN 128
#define HH 4
#define DKK 32
#define NW 64
#define LOG2E 1.4426950408889634f

// Scratch (no cudaMalloc allowed)
// g_hB: tf32 H^T in MMA-B fragment order:
//   slot = (((bh*16 + jt)*16 + kc)*4 + nt)*64 + d_loc*8 + 2*(j8&3) + (j8>>2)
//   where j = jt*128 + kc*8 + j8, d = nt*8 + d_loc.   (4 MB)
__device__ float g_hB[BB*HH*16*16*4*64];
__device__ float g_el[BB*HH*NN];           // pre-scaled by LOG2E
__device__ float g_er[BB*HH*NN];           // pre-scaled by LOG2E
__device__ unsigned g_bits[BB*NW*NN];      // transposed bitmask [b][wj][i]

// ---------------------------------------------------------------------------
// Kernel A: pack adj (67 MB, read once) -> transposed bitmask, 4x unrolled.
// ---------------------------------------------------------------------------
__global__ void pack_adj_k(const int* __restrict__ adj) {
    int gw    = (blockIdx.x * blockDim.x + threadIdx.x) >> 5;
    int lane  = threadIdx.x & 31;
    int nwrps = (gridDim.x * blockDim.x) >> 5;        // 16384
    const int total = BB * NW * NN;                   // 524288
    for (int base = gw; base < total; base += 4 * nwrps) {
        unsigned m[4];
#pragma unroll
        for (int k = 0; k < 4; k++) {
            int wdx = base + k * nwrps;
            int i  = wdx % NN;
            int wj = (wdx / NN) % NW;
            int b  = wdx / (NN * NW);
            int v = adj[((long long)(b * NN + i)) * NN + wj * 32 + lane];
            m[k] = __ballot_sync(0xffffffffu, v != 0);
        }
        if (lane == 0) {
#pragma unroll
            for (int k = 0; k < 4; k++) g_bits[base + k * nwrps] = m[k];
        }
    }
}

// ---------------------------------------------------------------------------
// Kernel B: h = x @ W. Writes fragment-ordered tf32 g_hB + fused el/er.
// ---------------------------------------------------------------------------
__global__ __launch_bounds__(256) void compute_h_k(const float* __restrict__ x,
                                                   const float* __restrict__ W,
                                                   const float* __restrict__ a) {
    __shared__ float xs[32][FIN];
    __shared__ float sT[128][33];
    int t = threadIdx.x, lane = t & 31;
    int row0 = blockIdx.x * 32;
    for (int idx = t; idx < 32 * FIN; idx += 256)
        xs[idx >> 7][idx & 127] = x[(long long)row0 * FIN + idx];
    __syncthreads();

    int c  = t & 127;
    int hh = c >> 5;
    int d  = c & 31;
    int rb = (t >> 7) * 16;

    float acc[16];
#pragma unroll
    for (int r = 0; r < 16; r++) acc[r] = 0.f;

    const float* Wc = W + hh * FIN * DKK + d;
    for (int i0 = 0; i0 < FIN; i0 += 4) {
        float w0 = __ldg(Wc + i0 * DKK);
        float w1 = __ldg(Wc + (i0 + 1) * DKK);
        float w2 = __ldg(Wc + (i0 + 2) * DKK);
        float w3 = __ldg(Wc + (i0 + 3) * DKK);
#pragma unroll
        for (int r = 0; r < 16; r++) {
            float4 xv = *(const float4*)&xs[rb + r][i0];
            acc[r] = fmaf(xv.x, w0, acc[r]);
            acc[r] = fmaf(xv.y, w1, acc[r]);
            acc[r] = fmaf(xv.z, w2, acc[r]);
            acc[r] = fmaf(xv.w, w3, acc[r]);
        }
    }

    int b  = row0 / NN;
    int n0 = row0 % NN;
    int bh = b * HH + hh;

    // fused el/er (full fp32 precision)
    float al = __ldg(a + hh * 2 * DKK + lane);
    float ar = __ldg(a + hh * 2 * DKK + DKK + lane);
#pragma unroll
    for (int r = 0; r < 16; r++) {
        float el = acc[r] * al, er = acc[r] * ar;
#pragma unroll
        for (int o = 16; o > 0; o >>= 1) {
            el += __shfl_xor_sync(0xffffffffu, el, o);
            er += __shfl_xor_sync(0xffffffffu, er, o);
        }
        if (lane == 0) {
            g_el[(long long)bh * NN + n0 + rb + r] = el * LOG2E;
            g_er[(long long)bh * NN + n0 + rb + r] = er * LOG2E;
        }
    }

    // tf32 round (rna) into transpose buffer
#pragma unroll
    for (int r = 0; r < 16; r++) {
        unsigned tv;
        asm("cvt.rna.tf32.f32 %0, %1;" : "=r"(tv) : "f"(acc[r]));
        sT[c][rb + r] = __uint_as_float(tv);
    }
    __syncthreads();

    // write g_hB in fragment order (coalesced STG.128).
    // B-fragment j order within each 8: position p = 2*(j&3) + (j>>2), so
    // positions [4*j4 .. 4*j4+3] hold j-values {2*j4, 2*j4+4, 2*j4+1, 2*j4+5}.
    // sT rows are 33 floats (odd pad) -> elements read SCALAR.
    int jt  = n0 >> 7;
    int kc0 = (n0 >> 3) & 15;
#pragma unroll
    for (int k = 0; k < 4; k++) {
        int q = t + k * 256;
        int j4    = q & 1;
        int d_loc = (q >> 1) & 7;
        int nt    = (q >> 4) & 3;
        int kcl   = (q >> 6) & 3;
        int h2    = q >> 8;
        int dd   = nt * 8 + d_loc;
        int base = kcl * 8;
        int row  = h2 * 32 + dd;
        float4 v = make_float4(sT[row][base + 2 * j4],
                               sT[row][base + 2 * j4 + 4],
                               sT[row][base + 2 * j4 + 1],
                               sT[row][base + 2 * j4 + 5]);
        long long off = ((((long long)((b * HH + h2) * 16 + jt) * 16 + (kc0 + kcl)) * 4 + nt) * 64)
                        + d_loc * 8 + j4 * 4;
        *(float4*)(g_hB + off) = v;
    }
}

// ---------------------------------------------------------------------------
// Kernel C: fused masked-softmax + aggregate via mma.sync tf32 m16n8k8.
// P generated in A fragments (raw fp32 bits; HW truncates to tf32 — the
// ones-column MMA sums the SAME truncated values, so softmax bias cancels).
// Row sums come from a 5th MMA with B = 1.0. B staged via linear f4 copy.
// ---------------------------------------------------------------------------
__device__ __forceinline__ unsigned p_gen(float el, float er, unsigned wrd, int pos) {
    float e = el + er;
    float l = fmaxf(e, 0.2f * e);
    float pe;
    asm("ex2.approx.f32 %0, %1;" : "=f"(pe) : "f"(l));
    unsigned bit;
    asm("bfe.u32 %0, %1, %2, 1;" : "=r"(bit) : "r"(wrd), "r"(pos));
    float p = bit ? pe : 0.f;
    return __float_as_uint(p);
}

#define MMA4(accp, A0, A1, A2, A3, B0, B1)                                    \
    asm("mma.sync.aligned.m16n8k8.row.col.f32.tf32.tf32.f32 "                 \
        "{%0,%1,%2,%3}, {%4,%5,%6,%7}, {%8,%9}, {%0,%1,%2,%3};"               \
        : "+f"((accp)[0]), "+f"((accp)[1]), "+f"((accp)[2]), "+f"((accp)[3])  \
        : "r"(A0), "r"(A1), "r"(A2), "r"(A3), "r"(B0), "r"(B1))

__global__ __launch_bounds__(256) void gat_attn_mma_k(float* __restrict__ out) {
    __shared__ float er_s[NN];     // 8 KB
    __shared__ float Bf[8192];     // 32 KB, flat fragment-ordered tiles

    int t = threadIdx.x, w = t >> 5, lane = t & 31;
    int bid = blockIdx.x;
    int it = bid & 31;
    int hh = (bid >> 5) & 3;
    int b  = bid >> 7;
    int bh = b * HH + hh;
    int ibase = it * 64;

    int half = w >> 2;
    int iw   = ibase + (w & 3) * 16;
    int r    = lane >> 2;
    int c0   = lane & 3;

    {
        float4* edst = (float4*)er_s;
        const float4* esrc = (const float4*)(g_er + (long long)bh * NN);
        edst[t] = esrc[t];
        edst[t + 256] = esrc[t + 256];
    }
    float el_lo = g_el[(long long)bh * NN + iw + r];
    float el_hi = g_el[(long long)bh * NN + iw + r + 8];

    float acc[4][4];
    float accS[4];
#pragma unroll
    for (int nt = 0; nt < 4; nt++)
#pragma unroll
        for (int q = 0; q < 4; q++) acc[nt][q] = 0.f;
#pragma unroll
    for (int q = 0; q < 4; q++) accS[q] = 0.f;

    const float* hBb = g_hB + (long long)bh * 65536;
    const unsigned* bitb = g_bits + (long long)b * NW * NN;
    const unsigned ONE = 0x3F800000u;

    for (int mt = 0; mt < 8; mt++) {
        __syncthreads();
        // linear coalesced staging: j-blocks mt (half 0) and mt+8 (half 1)
        {
            const float4* s0 = (const float4*)(hBb + mt * 4096);
            const float4* s1 = (const float4*)(hBb + (mt + 8) * 4096);
            float4* dst = (float4*)Bf;
#pragma unroll
            for (int k = 0; k < 4; k++) {
                dst[t + k * 256]        = s0[t + k * 256];
                dst[1024 + t + k * 256] = s1[t + k * 256];
            }
        }
        __syncthreads();

        unsigned wl = 0, wh = 0;
#pragma unroll 4
        for (int kc = 0; kc < 16; kc++) {
            if ((kc & 3) == 0) {
                int jw = half * 32 + mt * 4 + (kc >> 2);
                wl = bitb[(long long)jw * NN + iw + r];
                wh = bitb[(long long)jw * NN + iw + r + 8];
            }
            int eoff = half * 1024 + mt * 128 + kc * 8 + c0;
            float e0 = er_s[eoff];
            float e4 = er_s[eoff + 4];
            int j0 = (kc & 3) * 8 + c0;

            unsigned a0 = p_gen(el_lo, e0, wl, j0);
            unsigned a1 = p_gen(el_hi, e0, wh, j0);
            unsigned a2 = p_gen(el_lo, e4, wl, j0 + 4);
            unsigned a3 = p_gen(el_hi, e4, wh, j0 + 4);

            const float2* bp = (const float2*)(Bf + (half * 16 + kc) * 256) + lane;
#pragma unroll
            for (int nt = 0; nt < 4; nt++) {
                float2 bv = bp[nt * 32];
                MMA4(acc[nt], a0, a1, a2, a3,
                     __float_as_uint(bv.x), __float_as_uint(bv.y));
            }
            MMA4(accS, a0, a1, a2, a3, ONE, ONE);   // row sums
        }
    }

    // ---- combine the two j-halves (warps w and w+4) ----
    __syncthreads();
    float* red = Bf;
    if (w >= 4) {
        int base = ((w - 4) * 32 + lane) * 19;
#pragma unroll
        for (int nt = 0; nt < 4; nt++)
#pragma unroll
            for (int q = 0; q < 4; q++) red[base + nt * 4 + q] = acc[nt][q];
        red[base + 16] = accS[0];
        red[base + 17] = accS[2];
    }
    __syncthreads();
    if (w < 4) {
        int base = (w * 32 + lane) * 19;
#pragma unroll
        for (int nt = 0; nt < 4; nt++)
#pragma unroll
            for (int q = 0; q < 4; q++) acc[nt][q] += red[base + nt * 4 + q];
        float invl = 1.f / (accS[0] + red[base + 16]);
        float invh = 1.f / (accS[2] + red[base + 17]);

        float* ob = out + ((long long)bh * NN + iw + r) * DKK;
#pragma unroll
        for (int nt = 0; nt < 4; nt++) {
            int col = nt * 8 + 2 * c0;
            float2 v0 = make_float2(acc[nt][0] * invl, acc[nt][1] * invl);
            float2 v1 = make_float2(acc[nt][2] * invh, acc[nt][3] * invh);
            *(float2*)(ob + col) = v0;
            *(float2*)(ob + 8 * DKK + col) = v1;
        }
    }
}

// ---------------------------------------------------------------------------
extern "C" void kernel_launch(void* const* d_in, const int* in_sizes, int n_in,
                              void* d_out, int out_size) {
    const float* x   = (const float*)d_in[0];
    const int*   adj = (const int*)d_in[1];
    const float* W   = (const float*)d_in[2];
    const float* a   = (const float*)d_in[3];
    float* out = (float*)d_out;

    pack_adj_k<<<2048, 256>>>(adj);
    compute_h_k<<<(BB * NN) / 32, 256>>>(x, W, a);
    gat_attn_mma_k<<<BB * HH * 32, 256>>>(out);
}

// round 10
// speedup vs baseline: 2.7453x; 1.2045x over previous
#include <cuda_runtime.h>
#include <cstdint>

#define BB 4
#define NN 2048
#define FIN 128
#define HH 4
#define DKK 32
#define NW 64
#define LOG2E 1.4426950408889634f

// Scratch (no cudaMalloc allowed)
// g_hB: tf32 H^T in MMA-B fragment order:
//   slot = (((bh*16 + jt)*16 + kc)*4 + nt)*64 + d_loc*8 + 2*(j8&3) + (j8>>2)
__device__ float g_hB[BB*HH*16*16*4*64];
__device__ float g_el[BB*HH*NN];           // pre-scaled by LOG2E
__device__ float g_er[BB*HH*NN];           // pre-scaled by LOG2E
__device__ unsigned g_bits[BB*NW*NN];      // transposed bitmask [b][wj][i]

// ---------------------------------------------------------------------------
// Kernel A: pack adj -> transposed bitmask. One warp = (b, wj, 32-row chunk):
// 32 coalesced 128B row loads (MLP=32, constant-stride addressing), 32
// ballots, one coalesced STG.32 (lane k keeps ballot k).
// ---------------------------------------------------------------------------
__global__ __launch_bounds__(256) void pack_adj_k(const int* __restrict__ adj) {
    int t = threadIdx.x, w = t >> 5, lane = t & 31;
    int task = blockIdx.x * 8 + w;          // 16384 tasks
    int ic = task & 63;
    int wj = (task >> 6) & 63;
    int b  = task >> 12;
    int i0 = ic * 32;
    const int* src = adj + ((long long)(b * NN + i0)) * NN + wj * 32 + lane;
    unsigned mym = 0;
#pragma unroll
    for (int r = 0; r < 32; r++) {
        unsigned m = __ballot_sync(0xffffffffu, src[(long long)r * NN] != 0);
        if (lane == r) mym = m;
    }
    g_bits[((long long)(b * NW + wj)) * NN + i0 + lane] = mym;
}

// ---------------------------------------------------------------------------
// Kernel B: h = x @ W. Writes fragment-ordered tf32 g_hB + fused el/er.
// ---------------------------------------------------------------------------
__global__ __launch_bounds__(256) void compute_h_k(const float* __restrict__ x,
                                                   const float* __restrict__ W,
                                                   const float* __restrict__ a) {
    __shared__ float xs[32][FIN];
    __shared__ float sT[128][33];
    int t = threadIdx.x, lane = t & 31;
    int row0 = blockIdx.x * 32;
    for (int idx = t; idx < 32 * FIN; idx += 256)
        xs[idx >> 7][idx & 127] = x[(long long)row0 * FIN + idx];
    __syncthreads();

    int c  = t & 127;
    int hh = c >> 5;
    int d  = c & 31;
    int rb = (t >> 7) * 16;

    float acc[16];
#pragma unroll
    for (int r = 0; r < 16; r++) acc[r] = 0.f;

    const float* Wc = W + hh * FIN * DKK + d;
    for (int i0 = 0; i0 < FIN; i0 += 4) {
        float w0 = __ldg(Wc + i0 * DKK);
        float w1 = __ldg(Wc + (i0 + 1) * DKK);
        float w2 = __ldg(Wc + (i0 + 2) * DKK);
        float w3 = __ldg(Wc + (i0 + 3) * DKK);
#pragma unroll
        for (int r = 0; r < 16; r++) {
            float4 xv = *(const float4*)&xs[rb + r][i0];
            acc[r] = fmaf(xv.x, w0, acc[r]);
            acc[r] = fmaf(xv.y, w1, acc[r]);
            acc[r] = fmaf(xv.z, w2, acc[r]);
            acc[r] = fmaf(xv.w, w3, acc[r]);
        }
    }

    int b  = row0 / NN;
    int n0 = row0 % NN;
    int bh = b * HH + hh;

    // fused el/er (full fp32 precision)
    float al = __ldg(a + hh * 2 * DKK + lane);
    float ar = __ldg(a + hh * 2 * DKK + DKK + lane);
#pragma unroll
    for (int r = 0; r < 16; r++) {
        float el = acc[r] * al, er = acc[r] * ar;
#pragma unroll
        for (int o = 16; o > 0; o >>= 1) {
            el += __shfl_xor_sync(0xffffffffu, el, o);
            er += __shfl_xor_sync(0xffffffffu, er, o);
        }
        if (lane == 0) {
            g_el[(long long)bh * NN + n0 + rb + r] = el * LOG2E;
            g_er[(long long)bh * NN + n0 + rb + r] = er * LOG2E;
        }
    }

    // tf32 round (rna) into transpose buffer
#pragma unroll
    for (int r = 0; r < 16; r++) {
        unsigned tv;
        asm("cvt.rna.tf32.f32 %0, %1;" : "=r"(tv) : "f"(acc[r]));
        sT[c][rb + r] = __uint_as_float(tv);
    }
    __syncthreads();

    // write g_hB in fragment order (coalesced STG.128); interleaved j order:
    // positions [4*j4 .. 4*j4+3] hold j-values {2*j4, 2*j4+4, 2*j4+1, 2*j4+5}.
    int jt  = n0 >> 7;
    int kc0 = (n0 >> 3) & 15;
#pragma unroll
    for (int k = 0; k < 4; k++) {
        int q = t + k * 256;
        int j4    = q & 1;
        int d_loc = (q >> 1) & 7;
        int nt    = (q >> 4) & 3;
        int kcl   = (q >> 6) & 3;
        int h2    = q >> 8;
        int dd   = nt * 8 + d_loc;
        int base = kcl * 8;
        int row  = h2 * 32 + dd;
        float4 v = make_float4(sT[row][base + 2 * j4],
                               sT[row][base + 2 * j4 + 4],
                               sT[row][base + 2 * j4 + 1],
                               sT[row][base + 2 * j4 + 5]);
        long long off = ((((long long)((b * HH + h2) * 16 + jt) * 16 + (kc0 + kcl)) * 4 + nt) * 64)
                        + d_loc * 8 + j4 * 4;
        *(float4*)(g_hB + off) = v;
    }
}

// ---------------------------------------------------------------------------
// Kernel C: fused masked-softmax + aggregate via mma.sync tf32 m16n8k8.
// i-tile = 128: each warp owns 32 i-rows = 2 m16 tiles sharing B fragments.
// ---------------------------------------------------------------------------
__device__ __forceinline__ unsigned p_gen(float el, float er, unsigned wrd, int pos) {
    float e = el + er;
    float l = fmaxf(e, 0.2f * e);
    float pe;
    asm("ex2.approx.f32 %0, %1;" : "=f"(pe) : "f"(l));
    unsigned bit;
    asm("bfe.u32 %0, %1, %2, 1;" : "=r"(bit) : "r"(wrd), "r"(pos));
    float p = bit ? pe : 0.f;
    return __float_as_uint(p);
}

#define MMA4(accp, A0, A1, A2, A3, B0, B1)                                    \
    asm("mma.sync.aligned.m16n8k8.row.col.f32.tf32.tf32.f32 "                 \
        "{%0,%1,%2,%3}, {%4,%5,%6,%7}, {%8,%9}, {%0,%1,%2,%3};"               \
        : "+f"((accp)[0]), "+f"((accp)[1]), "+f"((accp)[2]), "+f"((accp)[3])  \
        : "r"(A0), "r"(A1), "r"(A2), "r"(A3), "r"(B0), "r"(B1))

__global__ __launch_bounds__(256) void gat_attn_mma_k(float* __restrict__ out) {
    __shared__ float er_s[NN];     // 8 KB
    __shared__ float Bf[8192];     // 32 KB, fragment tiles; reused as red buf

    int t = threadIdx.x, w = t >> 5, lane = t & 31;
    int bid = blockIdx.x;
    int it = bid & 15;                       // 16 i-tiles of 128
    int hh = (bid >> 4) & 3;
    int b  = bid >> 6;
    int bh = b * HH + hh;
    int ibase = it * 128;

    int half = w >> 2;
    int iw   = ibase + (w & 3) * 32;         // warp's 32 i-rows (2 m16 tiles)
    int r    = lane >> 2;
    int c0   = lane & 3;

    {
        float4* edst = (float4*)er_s;
        const float4* esrc = (const float4*)(g_er + (long long)bh * NN);
        edst[t] = esrc[t];
        edst[t + 256] = esrc[t + 256];
    }
    const float* elp = g_el + (long long)bh * NN + iw + r;
    float el0 = elp[0], el1 = elp[8], el2 = elp[16], el3 = elp[24];

    float acc[2][4][4];
    float accS[2][4];
#pragma unroll
    for (int m = 0; m < 2; m++) {
#pragma unroll
        for (int nt = 0; nt < 4; nt++)
#pragma unroll
            for (int q = 0; q < 4; q++) acc[m][nt][q] = 0.f;
#pragma unroll
        for (int q = 0; q < 4; q++) accS[m][q] = 0.f;
    }

    const float* hBb = g_hB + (long long)bh * 65536;
    const unsigned* bitb = g_bits + (long long)b * NW * NN;
    const unsigned ONE = 0x3F800000u;

    for (int mt = 0; mt < 8; mt++) {
        __syncthreads();
        {
            const float4* s0 = (const float4*)(hBb + mt * 4096);
            const float4* s1 = (const float4*)(hBb + (mt + 8) * 4096);
            float4* dst = (float4*)Bf;
#pragma unroll
            for (int k = 0; k < 4; k++) {
                dst[t + k * 256]        = s0[t + k * 256];
                dst[1024 + t + k * 256] = s1[t + k * 256];
            }
        }
        __syncthreads();

        unsigned w0a = 0, w0b = 0, w1a = 0, w1b = 0;
#pragma unroll 4
        for (int kc = 0; kc < 16; kc++) {
            if ((kc & 3) == 0) {
                int jw = half * 32 + mt * 4 + (kc >> 2);
                const unsigned* bp2 = bitb + (long long)jw * NN + iw + r;
                w0a = bp2[0];  w0b = bp2[8];
                w1a = bp2[16]; w1b = bp2[24];
            }
            int eoff = half * 1024 + mt * 128 + kc * 8 + c0;
            float e0 = er_s[eoff];
            float e4 = er_s[eoff + 4];
            int j0 = (kc & 3) * 8 + c0;

            unsigned a00 = p_gen(el0, e0, w0a, j0);
            unsigned a01 = p_gen(el1, e0, w0b, j0);
            unsigned a02 = p_gen(el0, e4, w0a, j0 + 4);
            unsigned a03 = p_gen(el1, e4, w0b, j0 + 4);
            unsigned a10 = p_gen(el2, e0, w1a, j0);
            unsigned a11 = p_gen(el3, e0, w1b, j0);
            unsigned a12 = p_gen(el2, e4, w1a, j0 + 4);
            unsigned a13 = p_gen(el3, e4, w1b, j0 + 4);

            const float2* bp = (const float2*)(Bf + (half * 16 + kc) * 256) + lane;
#pragma unroll
            for (int nt = 0; nt < 4; nt++) {
                float2 bv = bp[nt * 32];
                unsigned b0 = __float_as_uint(bv.x);
                unsigned b1 = __float_as_uint(bv.y);
                MMA4(acc[0][nt], a00, a01, a02, a03, b0, b1);
                MMA4(acc[1][nt], a10, a11, a12, a13, b0, b1);
            }
            MMA4(accS[0], a00, a01, a02, a03, ONE, ONE);
            MMA4(accS[1], a10, a11, a12, a13, ONE, ONE);
        }
    }

    // ---- combine the two j-halves (warps w and w+4) ----
    __syncthreads();
    float* red = Bf;
    if (w >= 4) {
        int base = ((w - 4) * 32 + lane) * 36;
#pragma unroll
        for (int m = 0; m < 2; m++) {
#pragma unroll
            for (int nt = 0; nt < 4; nt++)
#pragma unroll
                for (int q = 0; q < 4; q++)
                    red[base + m * 16 + nt * 4 + q] = acc[m][nt][q];
            red[base + 32 + m * 2]     = accS[m][0];
            red[base + 32 + m * 2 + 1] = accS[m][2];
        }
    }
    __syncthreads();
    if (w < 4) {
        int base = (w * 32 + lane) * 36;
#pragma unroll
        for (int m = 0; m < 2; m++) {
#pragma unroll
            for (int nt = 0; nt < 4; nt++)
#pragma unroll
                for (int q = 0; q < 4; q++)
                    acc[m][nt][q] += red[base + m * 16 + nt * 4 + q];
            float invl = 1.f / (accS[m][0] + red[base + 32 + m * 2]);
            float invh = 1.f / (accS[m][2] + red[base + 32 + m * 2 + 1]);

            float* ob = out + ((long long)bh * NN + iw + m * 16 + r) * DKK;
#pragma unroll
            for (int nt = 0; nt < 4; nt++) {
                int col = nt * 8 + 2 * c0;
                float2 v0 = make_float2(acc[m][nt][0] * invl, acc[m][nt][1] * invl);
                float2 v1 = make_float2(acc[m][nt][2] * invh, acc[m][nt][3] * invh);
                *(float2*)(ob + col) = v0;
                *(float2*)(ob + 8 * DKK + col) = v1;
            }
        }
    }
}

// ---------------------------------------------------------------------------
extern "C" void kernel_launch(void* const* d_in, const int* in_sizes, int n_in,
                              void* d_out, int out_size) {
    const float* x   = (const float*)d_in[0];
    const int*   adj = (const int*)d_in[1];
    const float* W   = (const float*)d_in[2];
    const float* a   = (const float*)d_in[3];
    float* out = (float*)d_out;

    pack_adj_k<<<2048, 256>>>(adj);
    compute_h_k<<<(BB * NN) / 32, 256>>>(x, W, a);
    gat_attn_mma_k<<<BB * HH * 16, 256>>>(out);
}